// round 6
// baseline (speedup 1.0000x reference)
#include <cuda_runtime.h>
#include <cstdint>

// Problem constants (fixed shapes from reference)
#define T_IMG 15
#define C1    6
#define HW    224
#define O1    30
#define O2    240
#define PH    112                      // pooled / layer-2 spatial size
#define N2    (T_IMG*O2*PH*PH)         // 45,158,400 elements per output tensor
#define ZCAP  (T_IMG*O1*PH*PH)         // max possible zero-spike entries
#define IN_TILE_H 36
#define IN_TILE_W 36

// Scratch (device globals — no allocation allowed)
__device__ float d_S[O2*9];            // per-o border-class full sums of w2
__device__ int   d_zero_count;
__device__ int   d_zero_list[ZCAP];

typedef unsigned long long u64;

__device__ __forceinline__ u64 pk2(float lo, float hi) {
    u64 r; asm("mov.b64 %0, {%1,%2};" : "=l"(r) : "f"(lo), "f"(hi)); return r;
}
__device__ __forceinline__ void fma2(u64 &d, u64 a, u64 b) {
    asm("fma.rn.f32x2 %0, %1, %2, %0;" : "+l"(d) : "l"(a), "l"(b));
}
__device__ __forceinline__ float2 unpk(u64 v) {
    float2 f; asm("mov.b64 {%0,%1}, %2;" : "=f"(f.x), "=f"(f.y) : "l"(v)); return f;
}

// ---------------------------------------------------------------------------
// prep: zero the zero-spike counter, build S[o][rc][cc] =
//   sum over allowed (kh,kw) (border classes from zero padding) and all c of w2
// rc/cc class: 0 -> coord==0 (pad row 0 dead, k in {1,2})
//              1 -> interior (all k)
//              2 -> coord==111 (pad row 113 dead, k in {0,1})
// ---------------------------------------------------------------------------
__global__ void prep_kernel(const float* __restrict__ w2) {
    int o = blockIdx.x;
    int j = threadIdx.x;
    if (o == 0 && j == 9) d_zero_count = 0;
    if (j < 9) {
        int rc = j / 3, cc = j % 3;
        int kh_lo = (rc == 0) ? 1 : 0;
        int kh_hi = (rc == 2) ? 1 : 2;
        int kw_lo = (cc == 0) ? 1 : 0;
        int kw_hi = (cc == 2) ? 1 : 2;
        float s = 0.f;
        for (int kh = kh_lo; kh <= kh_hi; ++kh)
            for (int kw = kw_lo; kw <= kw_hi; ++kw)
                for (int c = 0; c < O1; ++c)
                    s += w2[((o*O1 + c)*3 + kh)*3 + kw];
        d_S[o*9 + j] = s;
    }
}

// ---------------------------------------------------------------------------
// conv1 + fire(15) + maxpool(2,2), fused. Only NON-firing pooled pixels are
// recorded (appended to d_zero_list) — the spikes themselves are implied 1.
// Packed fp32x2 FMA: each thread computes a horizontal pair of pooled pixels
// (= 2x4 conv outputs) for 5 output channels per group, 6 groups.
// Block: 128 threads = 8(x-pairs) x 16(y), conv tile 32x32, pooled tile 16x16.
// ---------------------------------------------------------------------------
__global__ void __launch_bounds__(128) conv1_kernel(
    const float* __restrict__ in, const float* __restrict__ w1)
{
    __shared__ float s_in[C1][IN_TILE_H][IN_TILE_W];   // 31,104 B
    __shared__ float s_w[O1*C1*25];                    // 18,000 B  (total 49,104 <= 48KB)

    const int t  = blockIdx.z;
    const int by = blockIdx.y, bx = blockIdx.x;
    const int tid = threadIdx.x;

    const float* inp = in + (size_t)t * C1 * HW * HW;
    for (int idx = tid; idx < C1*IN_TILE_H*IN_TILE_W; idx += 128) {
        int c   = idx / (IN_TILE_H*IN_TILE_W);
        int rem = idx % (IN_TILE_H*IN_TILE_W);
        int r   = rem / IN_TILE_W, col = rem % IN_TILE_W;
        int gy  = by*32 - 2 + r, gx = bx*32 - 2 + col;
        float v = 0.f;
        if ((unsigned)gy < HW && (unsigned)gx < HW) v = inp[(c*HW + gy)*HW + gx];
        s_in[c][r][col] = v;
    }
    for (int idx = tid; idx < O1*C1*25; idx += 128) s_w[idx] = w1[idx];
    __syncthreads();

    const int tx = tid & 7, ty = tid >> 3;
    const int r0 = 2*ty, c0 = 4*tx;
    const int PY  = by*16 + ty;
    const int PX0 = bx*16 + 2*tx;

    for (int g = 0; g < 6; ++g) {
        u64 accA[5], accB[5], accC[5], accD[5];
        #pragma unroll
        for (int o = 0; o < 5; ++o) { accA[o]=0ull; accB[o]=0ull; accC[o]=0ull; accD[o]=0ull; }

        #pragma unroll
        for (int c = 0; c < C1; ++c) {
            #pragma unroll
            for (int kh = 0; kh < 5; ++kh) {
                const float* ra = &s_in[c][r0+kh][c0];
                const float* rb = ra + IN_TILE_W;
                float2 a01 = *(const float2*)(ra+0);
                float2 a23 = *(const float2*)(ra+2);
                float2 a45 = *(const float2*)(ra+4);
                float2 a67 = *(const float2*)(ra+6);
                float2 b01 = *(const float2*)(rb+0);
                float2 b23 = *(const float2*)(rb+2);
                float2 b45 = *(const float2*)(rb+4);
                float2 b67 = *(const float2*)(rb+6);
                u64 pa[7], pb[7];
                pa[0]=pk2(a01.x,a01.y); pa[1]=pk2(a01.y,a23.x); pa[2]=pk2(a23.x,a23.y);
                pa[3]=pk2(a23.y,a45.x); pa[4]=pk2(a45.x,a45.y); pa[5]=pk2(a45.y,a67.x);
                pa[6]=pk2(a67.x,a67.y);
                pb[0]=pk2(b01.x,b01.y); pb[1]=pk2(b01.y,b23.x); pb[2]=pk2(b23.x,b23.y);
                pb[3]=pk2(b23.y,b45.x); pb[4]=pk2(b45.x,b45.y); pb[5]=pk2(b45.y,b67.x);
                pb[6]=pk2(b67.x,b67.y);

                #pragma unroll
                for (int o = 0; o < 5; ++o) {
                    const float* wp = &s_w[((g*5+o)*C1 + c)*25 + kh*5];
                    #pragma unroll
                    for (int kw = 0; kw < 5; ++kw) {
                        u64 w2x = pk2(wp[kw], wp[kw]);
                        fma2(accA[o], w2x, pa[kw]);
                        fma2(accB[o], w2x, pb[kw]);
                        fma2(accC[o], w2x, pa[kw+2]);
                        fma2(accD[o], w2x, pb[kw+2]);
                    }
                }
            }
        }

        #pragma unroll
        for (int o = 0; o < 5; ++o) {
            float2 fa = unpk(accA[o]), fb = unpk(accB[o]);
            float2 fc = unpk(accC[o]), fd = unpk(accD[o]);
            float m0 = fmaxf(fmaxf(fa.x, fb.x), fmaxf(fa.y, fb.y));
            float m1 = fmaxf(fmaxf(fc.x, fd.x), fmaxf(fc.y, fd.y));
            int ch = g*5 + o;
            if (!(m0 > 15.0f)) {
                int s = atomicAdd(&d_zero_count, 1);
                d_zero_list[s] = ((t*O1 + ch)*PH + PY)*PH + PX0;
            }
            if (!(m1 > 15.0f)) {
                int s = atomicAdd(&d_zero_count, 1);
                d_zero_list[s] = ((t*O1 + ch)*PH + PY)*PH + PX0 + 1;
            }
        }
    }
}

// ---------------------------------------------------------------------------
// fill: pot2 assuming all pooled spikes fire = S[o][rc(y)][cc(x)].
// One float4 per thread, fully coalesced (28 float4 per 112-wide row).
// ---------------------------------------------------------------------------
__global__ void fill_kernel(float* __restrict__ pot) {
    int i = blockIdx.x*blockDim.x + threadIdx.x;
    if (i >= N2/4) return;
    int row = i / 28;            // (t*240 + o)*112 + y
    int xq  = i % 28;
    int y = row % PH;
    int o = (row / PH) % O2;
    int rc = (y == 0) ? 0 : ((y == PH-1) ? 2 : 1);
    const float* Sp = &d_S[o*9 + rc*3];
    float v0 = Sp[0], v1 = Sp[1], v2 = Sp[2];
    float4 outv;
    outv.x = (xq == 0)  ? v0 : v1;
    outv.y = v1;
    outv.z = v1;
    outv.w = (xq == 27) ? v2 : v1;
    ((float4*)pot)[i] = outv;
}

// ---------------------------------------------------------------------------
// correct: for each recorded zero pooled spike (t,c,py,px), subtract its w2
// contribution from the <=3x3 affected output pixels across all 240 channels.
// Exact; no-op when the list is empty.
// ---------------------------------------------------------------------------
__global__ void correct_kernel(const float* __restrict__ w2, float* __restrict__ pot) {
    int total  = d_zero_count * O2;
    int stride = gridDim.x * blockDim.x;
    for (int i = blockIdx.x*blockDim.x + threadIdx.x; i < total; i += stride) {
        int e = i / O2, o = i % O2;
        int packed = d_zero_list[e];
        int px = packed % PH;
        int py = (packed / PH) % PH;
        int c  = (packed / (PH*PH)) % O1;
        int t  =  packed / (PH*PH*O1);
        float* potbase = pot + ((size_t)(t*O2 + o))*PH*PH;
        const float* wb = w2 + (o*O1 + c)*9;
        #pragma unroll
        for (int kh = 0; kh < 3; ++kh) {
            int y = py + 1 - kh;
            if ((unsigned)y >= PH) continue;
            #pragma unroll
            for (int kw = 0; kw < 3; ++kw) {
                int x = px + 1 - kw;
                if ((unsigned)x >= PH) continue;
                atomicAdd(&potbase[y*PH + x], -wb[kh*3 + kw]);
            }
        }
    }
}

// ---------------------------------------------------------------------------
// finalize: spk = (pot > 10) ? 1 : 0 ; pot = (pot > 10) ? pot : 0.
// Pot rewrite only when something changed (rare) -> saves ~181 MB of writes.
// ---------------------------------------------------------------------------
__global__ void finalize_kernel(float* __restrict__ spk, float* __restrict__ pot) {
    int i = blockIdx.x*blockDim.x + threadIdx.x;
    if (i >= N2/4) return;
    float4 p = ((const float4*)pot)[i];
    bool fx = p.x > 10.0f, fy = p.y > 10.0f, fz = p.z > 10.0f, fw = p.w > 10.0f;
    float4 s;
    s.x = fx ? 1.0f : 0.0f;
    s.y = fy ? 1.0f : 0.0f;
    s.z = fz ? 1.0f : 0.0f;
    s.w = fw ? 1.0f : 0.0f;
    ((float4*)spk)[i] = s;
    if (!(fx && fy && fz && fw)) {
        if (!fx) p.x = 0.0f;
        if (!fy) p.y = 0.0f;
        if (!fz) p.z = 0.0f;
        if (!fw) p.w = 0.0f;
        ((float4*)pot)[i] = p;
    }
}

// ---------------------------------------------------------------------------
extern "C" void kernel_launch(void* const* d_in, const int* in_sizes, int n_in,
                              void* d_out, int out_size) {
    const float* input = (const float*)d_in[0];
    const float* w1    = (const float*)d_in[1];
    const float* w2    = (const float*)d_in[2];
    // output = concat(spk, pot), each out_size/2 floats
    float* spk = (float*)d_out;
    float* pot = spk + (size_t)(out_size / 2);

    prep_kernel<<<O2, 32>>>(w2);
    conv1_kernel<<<dim3(7, 7, T_IMG), 128>>>(input, w1);
    const int n4 = N2 / 4;
    fill_kernel<<<(n4 + 255)/256, 256>>>(pot);
    correct_kernel<<<960, 256>>>(w2, pot);
    finalize_kernel<<<(n4 + 255)/256, 256>>>(spk, pot);
    (void)in_sizes; (void)n_in;
}

// round 7
// speedup vs baseline: 1.9171x; 1.9171x over previous
#include <cuda_runtime.h>
#include <cstdint>

// Problem constants (fixed shapes from reference)
#define T_IMG 15
#define C1    6
#define HW    224
#define O1    30
#define O2    240
#define PH    112                      // pooled / layer-2 spatial size
#define N2    (T_IMG*O2*PH*PH)         // 45,158,400 elements per output tensor
#define ZCAP  (T_IMG*O1*PH*PH)
#define CCAP  (1<<22)

// Scratch (device globals — no allocation allowed)
__device__ float d_S[O2*9];            // per-o border-class full sums of w2
__device__ int   d_zero_count;
__device__ int   d_zero_list[ZCAP];
__device__ int   d_cand_count;
__device__ int   d_cand_list[CCAP];

typedef unsigned long long u64;

__device__ __forceinline__ u64 pk2(float lo, float hi) {
    u64 r; asm("mov.b64 %0, {%1,%2};" : "=l"(r) : "f"(lo), "f"(hi)); return r;
}
__device__ __forceinline__ void fma2(u64 &d, u64 a, u64 b) {
    asm("fma.rn.f32x2 %0, %1, %2, %0;" : "+l"(d) : "l"(a), "l"(b));
}
__device__ __forceinline__ float2 unpk(u64 v) {
    float2 f; asm("mov.b64 {%0,%1}, %2;" : "=f"(f.x), "=f"(f.y) : "l"(v)); return f;
}

// ---------------------------------------------------------------------------
// prep: zero counters; build S[o][rc][cc] = sum over border-allowed (kh,kw)
// and all c of w2 (zero-padding kills kernel rows/cols at the edges).
// ---------------------------------------------------------------------------
__global__ void prep_kernel(const float* __restrict__ w2) {
    int o = blockIdx.x;
    int j = threadIdx.x;
    if (o == 0 && j == 9)  d_zero_count = 0;
    if (o == 0 && j == 10) d_cand_count = 0;
    if (j < 9) {
        int rc = j / 3, cc = j % 3;
        int kh_lo = (rc == 0) ? 1 : 0;
        int kh_hi = (rc == 2) ? 1 : 2;
        int kw_lo = (cc == 0) ? 1 : 0;
        int kw_hi = (cc == 2) ? 1 : 2;
        float s = 0.f;
        for (int kh = kh_lo; kh <= kh_hi; ++kh)
            for (int kw = kw_lo; kw <= kw_hi; ++kw)
                for (int c = 0; c < O1; ++c)
                    s += w2[((o*O1 + c)*3 + kh)*3 + kw];
        d_S[o*9 + j] = s;
    }
}

// ---------------------------------------------------------------------------
// conv1 v2: representative-pixel strategy. A pooled pixel (py,px) fires if
// ANY of its 4 conv pixels > 15. We compute ONLY conv pixel (2py,2px) for all
// channels (1/4 of the work). If it fires -> pooled spike = 1 for sure
// (monotone max). If not (rare), append a candidate; fallback_kernel resolves
// it exactly with all 4 pixels.
//
// Block: 160 threads = 5 warps (one 6-channel output group per warp, so the
// weight LDS is a uniform broadcast). Warp lanes: pyl(2) x xi(16, 14 active).
// Each thread: 8 pooled px as 4 f32x2 pairs x 6 output channels.
// Grid: (56 row-bands of 2 pooled rows, 15 t). Dynamic smem 57KB.
// ---------------------------------------------------------------------------
__global__ void __launch_bounds__(160) conv1_kernel(
    const float* __restrict__ in, const float* __restrict__ w1)
{
    extern __shared__ float sm[];
    float* s_w  = sm;          // 30*6*25 = 4500 floats
    float* s_in = sm + 4512;   // 6 ch * 7 rows * 232 stride = 9744 floats

    const int band = blockIdx.x;   // 0..55 (2 pooled rows each)
    const int t    = blockIdx.y;   // 0..14
    const int tid  = threadIdx.x;

    // load input slab: rows 4*band-2 .. 4*band+4, cols -2..225 (zero padded)
    const float* inp = in + (size_t)t * C1 * HW * HW;
    for (int idx = tid; idx < C1*7*228; idx += 160) {
        int c   = idx / (7*228);
        int rem = idx % (7*228);
        int r   = rem / 228, col = rem % 228;
        int gy  = 4*band - 2 + r, gx = col - 2;
        float v = 0.f;
        if ((unsigned)gy < HW && (unsigned)gx < HW) v = inp[(c*HW + gy)*HW + gx];
        s_in[(c*7 + r)*232 + col] = v;
    }
    for (int idx = tid; idx < O1*C1*25; idx += 160) s_w[idx] = w1[idx];
    __syncthreads();

    const int og  = tid >> 5;        // 0..4 : output channel group (6 ch)
    const int w   = tid & 31;
    const int pyl = w >> 4;          // 0..1 : pooled row within band
    const int xi  = w & 15;          // 0..15; active < 14
    if (xi >= 14) return;            // (no further barriers)

    const int X0 = 16*xi;            // conv x of first pixel this thread owns
    const int py = band*2 + pyl;

    u64 acc[4][6];
    #pragma unroll
    for (int p = 0; p < 4; ++p)
        #pragma unroll
        for (int och = 0; och < 6; ++och) acc[p][och] = 0ull;

    #pragma unroll
    for (int c = 0; c < C1; ++c) {
        #pragma unroll
        for (int kh = 0; kh < 5; ++kh) {
            const float* row = &s_in[(c*7 + 2*pyl + kh)*232 + X0];
            float v[19];
            #pragma unroll
            for (int j = 0; j < 19; ++j) v[j] = row[j];
            u64 pk[17];
            #pragma unroll
            for (int j = 0; j < 17; ++j) pk[j] = pk2(v[j], v[j+2]);

            #pragma unroll
            for (int och = 0; och < 6; ++och) {
                const float* wq = &s_w[((og*6 + och)*C1 + c)*25 + kh*5];
                #pragma unroll
                for (int kw = 0; kw < 5; ++kw) {
                    u64 ws = pk2(wq[kw], wq[kw]);
                    fma2(acc[0][och], ws, pk[kw]);
                    fma2(acc[1][och], ws, pk[4 + kw]);
                    fma2(acc[2][och], ws, pk[8 + kw]);
                    fma2(acc[3][och], ws, pk[12 + kw]);
                }
            }
        }
    }

    #pragma unroll
    for (int och = 0; och < 6; ++och) {
        int o = og*6 + och;
        #pragma unroll
        for (int p = 0; p < 4; ++p) {
            float2 f = unpk(acc[p][och]);
            int px = 8*xi + 2*p;
            if (!(f.x > 15.0f)) {
                int s = atomicAdd(&d_cand_count, 1);
                if (s < CCAP) d_cand_list[s] = ((t*O1 + o)*PH + py)*PH + px;
            }
            if (!(f.y > 15.0f)) {
                int s = atomicAdd(&d_cand_count, 1);
                if (s < CCAP) d_cand_list[s] = ((t*O1 + o)*PH + py)*PH + px + 1;
            }
        }
    }
}

// ---------------------------------------------------------------------------
// fallback: for each candidate pooled pixel, compute the full 2x2 conv-pixel
// max exactly from gmem; if the max doesn't fire, record a true zero spike.
// Expected empty -> ~launch overhead only.
// ---------------------------------------------------------------------------
__global__ void fallback_kernel(const float* __restrict__ in,
                                const float* __restrict__ w1)
{
    int n = d_cand_count; if (n > CCAP) n = CCAP;
    int stride = gridDim.x * blockDim.x;
    for (int i = blockIdx.x*blockDim.x + threadIdx.x; i < n; i += stride) {
        int packed = d_cand_list[i];
        int px = packed % PH;
        int py = (packed / PH) % PH;
        int ch = (packed / (PH*PH)) % O1;
        int t  =  packed / (PH*PH*O1);
        float m = -1e30f;
        for (int yy = 0; yy < 2; ++yy) {
            for (int xx = 0; xx < 2; ++xx) {
                float pot = 0.f;
                for (int c = 0; c < C1; ++c)
                    for (int kh = 0; kh < 5; ++kh) {
                        int iy = 2*py + yy - 2 + kh;
                        if ((unsigned)iy >= HW) continue;
                        for (int kw = 0; kw < 5; ++kw) {
                            int ix = 2*px + xx - 2 + kw;
                            if ((unsigned)ix >= HW) continue;
                            pot += in[(((size_t)t*C1 + c)*HW + iy)*HW + ix]
                                 * w1[((ch*C1 + c)*5 + kh)*5 + kw];
                        }
                    }
                m = fmaxf(m, pot);
            }
        }
        if (!(m > 15.0f)) {
            int s = atomicAdd(&d_zero_count, 1);
            d_zero_list[s] = packed;
        }
    }
}

// ---------------------------------------------------------------------------
// fused fill + finalize: pot2 assuming all pooled spikes fire = S[o][rc][cc],
// thresholded at 10; writes BOTH pot and spk in one pass (no read-back pass).
// 362 MB pure writes, fully coalesced float4.
// ---------------------------------------------------------------------------
__global__ void fill_fin_kernel(float* __restrict__ spk, float* __restrict__ pot) {
    int i = blockIdx.x*blockDim.x + threadIdx.x;
    if (i >= N2/4) return;
    int row = i / 28;            // (t*240 + o)*112 + y
    int xq  = i % 28;
    int y = row % PH;
    int o = (row / PH) % O2;
    int rc = (y == 0) ? 0 : ((y == PH-1) ? 2 : 1);
    const float* Sp = &d_S[o*9 + rc*3];
    float v0 = Sp[0], v1 = Sp[1], v2 = Sp[2];
    float4 p;
    p.x = (xq == 0)  ? v0 : v1;
    p.y = v1; p.z = v1;
    p.w = (xq == 27) ? v2 : v1;
    float4 s;
    s.x = (p.x > 10.0f) ? 1.0f : 0.0f; if (!(p.x > 10.0f)) p.x = 0.0f;
    s.y = (p.y > 10.0f) ? 1.0f : 0.0f; if (!(p.y > 10.0f)) p.y = 0.0f;
    s.z = (p.z > 10.0f) ? 1.0f : 0.0f; if (!(p.z > 10.0f)) p.z = 0.0f;
    s.w = (p.w > 10.0f) ? 1.0f : 0.0f; if (!(p.w > 10.0f)) p.w = 0.0f;
    ((float4*)spk)[i] = s;
    ((float4*)pot)[i] = p;
}

// ---------------------------------------------------------------------------
// correct: subtract each recorded zero-spike's w2 contribution from the <=3x3
// affected pot pixels across all 240 channels. Base pot is the thresholded S:
//   S>10 -> exact subtraction on S, fixed up below;
//   S<=10 -> base 0, result <=0, fixup clamps to 0 (true value also 0). Exact.
// ---------------------------------------------------------------------------
__global__ void correct_kernel(const float* __restrict__ w2, float* __restrict__ pot) {
    int total  = d_zero_count * O2;
    int stride = gridDim.x * blockDim.x;
    for (int i = blockIdx.x*blockDim.x + threadIdx.x; i < total; i += stride) {
        int e = i / O2, o = i % O2;
        int packed = d_zero_list[e];
        int px = packed % PH;
        int py = (packed / PH) % PH;
        int c  = (packed / (PH*PH)) % O1;
        int t  =  packed / (PH*PH*O1);
        float* potbase = pot + ((size_t)(t*O2 + o))*PH*PH;
        const float* wb = w2 + (o*O1 + c)*9;
        #pragma unroll
        for (int kh = 0; kh < 3; ++kh) {
            int y = py + 1 - kh;
            if ((unsigned)y >= PH) continue;
            #pragma unroll
            for (int kw = 0; kw < 3; ++kw) {
                int x = px + 1 - kw;
                if ((unsigned)x >= PH) continue;
                atomicAdd(&potbase[y*PH + x], -wb[kh*3 + kw]);
            }
        }
    }
}

// ---------------------------------------------------------------------------
// fixup: only runs real work if corrections happened. Re-thresholds pot and
// rewrites spk for the whole tensor (idempotent for untouched pixels).
// When d_zero_count == 0 every block exits after one cached global read.
// ---------------------------------------------------------------------------
__global__ void fixup_kernel(float* __restrict__ spk, float* __restrict__ pot) {
    if (d_zero_count == 0) return;
    const int n4 = N2/4;
    int stride = gridDim.x * blockDim.x;
    for (int i = blockIdx.x*blockDim.x + threadIdx.x; i < n4; i += stride) {
        float4 p = ((const float4*)pot)[i];
        float4 s;
        s.x = (p.x > 10.0f) ? 1.0f : 0.0f; if (!(p.x > 10.0f)) p.x = 0.0f;
        s.y = (p.y > 10.0f) ? 1.0f : 0.0f; if (!(p.y > 10.0f)) p.y = 0.0f;
        s.z = (p.z > 10.0f) ? 1.0f : 0.0f; if (!(p.z > 10.0f)) p.z = 0.0f;
        s.w = (p.w > 10.0f) ? 1.0f : 0.0f; if (!(p.w > 10.0f)) p.w = 0.0f;
        ((float4*)spk)[i] = s;
        ((float4*)pot)[i] = p;
    }
}

// ---------------------------------------------------------------------------
extern "C" void kernel_launch(void* const* d_in, const int* in_sizes, int n_in,
                              void* d_out, int out_size) {
    const float* input = (const float*)d_in[0];
    const float* w1    = (const float*)d_in[1];
    const float* w2    = (const float*)d_in[2];
    float* spk = (float*)d_out;
    float* pot = spk + (size_t)(out_size / 2);

    const int conv1_smem = (4512 + 6*7*232) * 4;   // 57,024 B
    cudaFuncSetAttribute(conv1_kernel,
                         cudaFuncAttributeMaxDynamicSharedMemorySize, conv1_smem);

    prep_kernel<<<O2, 32>>>(w2);
    conv1_kernel<<<dim3(56, T_IMG), 160, conv1_smem>>>(input, w1);
    fallback_kernel<<<128, 128>>>(input, w1);
    const int n4 = N2 / 4;
    fill_fin_kernel<<<(n4 + 255)/256, 256>>>(spk, pot);
    correct_kernel<<<960, 256>>>(w2, pot);
    fixup_kernel<<<2048, 256>>>(spk, pot);
    (void)in_sizes; (void)n_in;
}

// round 8
// speedup vs baseline: 3.6163x; 1.8863x over previous
#include <cuda_runtime.h>
#include <cstdint>

// Problem constants (fixed shapes from reference)
#define T_IMG 15
#define C1    6
#define HW    224
#define O1    30
#define O2    240
#define PH    112                      // pooled / layer-2 spatial size
#define N2    (T_IMG*O2*PH*PH)         // 45,158,400 elements per output tensor
#define ZCAP  (T_IMG*O1*PH*PH)
#define CCAP  (1<<22)
#define SCREEN_BLOCKS (T_IMG*PH)       // 1680

// Scratch (device globals — no allocation allowed)
__device__ float d_S[O2*9];            // per-o border-class full sums of w2
__device__ float d_wmin[O1];           // min weight of each conv1 filter
__device__ int   d_zero_count;
__device__ int   d_zero_list[ZCAP];
__device__ int   d_cand_count;
__device__ int   d_cand_list[CCAP];

// ---------------------------------------------------------------------------
// prep: zero counters; build S[o][rc][cc] (border-class full sums of w2 for
// the all-spikes-fire analytic pot2); compute wmin_o over each conv1 filter.
// ---------------------------------------------------------------------------
__global__ void prep_kernel(const float* __restrict__ w1,
                            const float* __restrict__ w2) {
    int o = blockIdx.x;
    int j = threadIdx.x;
    if (o < O2) {
        if (o == 0 && j == 9)  d_zero_count = 0;
        if (o == 0 && j == 10) d_cand_count = 0;
        if (j < 9) {
            int rc = j / 3, cc = j % 3;
            int kh_lo = (rc == 0) ? 1 : 0;
            int kh_hi = (rc == 2) ? 1 : 2;
            int kw_lo = (cc == 0) ? 1 : 0;
            int kw_hi = (cc == 2) ? 1 : 2;
            float s = 0.f;
            for (int kh = kh_lo; kh <= kh_hi; ++kh)
                for (int kw = kw_lo; kw <= kw_hi; ++kw)
                    for (int c = 0; c < O1; ++c)
                        s += w2[((o*O1 + c)*3 + kh)*3 + kw];
            d_S[o*9 + j] = s;
        }
    } else {
        // block O2: per-filter min of w1 (30 filters x 150 weights)
        if (j < O1) {
            const float* w = w1 + j*(C1*25);
            float m = w[0];
            for (int k = 1; k < C1*25; ++k) m = fminf(m, w[k]);
            d_wmin[j] = m;
        }
    }
}

// ---------------------------------------------------------------------------
// fused kernel, two block roles:
//
// SCREEN blocks (bid < 1680): one (t, pooled row py) each. For every pooled
//   px, compute B = zero-padded 5x5x6 box-sum of the input at the
//   representative conv pixel (2py,2px). Since input >= 0,
//   pot_o(rep) >= wmin_o * B; if that exceeds 15 the pooled pixel provably
//   fires (max over 2x2 >= rep). Otherwise (t,o,py,px) becomes a candidate
//   resolved exactly by fallback_kernel. Negative wmin_o => product <= 0 =>
//   always candidate => sound for any weights.
//
// FILL blocks (bid >= 1680): pot2 assuming all pooled spikes fire =
//   S[o][rc(y)][cc(x)], thresholded at 10; writes BOTH pot and spk in one
//   coalesced float4 pass (no read-back). DRAM-bound; screen work hides
//   under it.
// ---------------------------------------------------------------------------
__global__ void __launch_bounds__(256) fused_kernel(
    const float* __restrict__ in,
    float* __restrict__ spk, float* __restrict__ pot)
{
    __shared__ float sV[228];
    __shared__ float swmin[O1];
    __shared__ float swminmin;

    const int bid = blockIdx.x;
    const int tid = threadIdx.x;

    if (bid < SCREEN_BLOCKS) {
        const int t  = bid / PH;
        const int py = bid % PH;

        if (tid < O1) swmin[tid] = d_wmin[tid];
        __syncthreads();
        if (tid == 0) {
            float m = swmin[0];
            #pragma unroll
            for (int o = 1; o < O1; ++o) m = fminf(m, swmin[o]);
            swminmin = m;
        }

        // column sums over the 5 conv rows x 6 channels (zero padding)
        const float* base = in + (size_t)t * C1*HW*HW;
        if (tid < 228) {
            int x = tid - 2;
            float s = 0.f;
            if ((unsigned)x < HW) {
                int y0 = 2*py - 2;
                #pragma unroll
                for (int r = 0; r < 5; ++r) {
                    int y = y0 + r;
                    if ((unsigned)y < HW) {
                        #pragma unroll
                        for (int c = 0; c < C1; ++c)
                            s += base[(c*HW + y)*HW + x];
                    }
                }
            }
            sV[tid] = s;
        }
        __syncthreads();

        if (tid >= PH) return;
        const int px = tid;
        float B = sV[2*px] + sV[2*px+1] + sV[2*px+2] + sV[2*px+3] + sV[2*px+4];
        if (swminmin * B > 15.0f) return;     // every filter provably fires
        for (int o = 0; o < O1; ++o) {
            if (!(swmin[o] * B > 15.0f)) {
                int s = atomicAdd(&d_cand_count, 1);
                if (s < CCAP) d_cand_list[s] = ((t*O1 + o)*PH + py)*PH + px;
            }
        }
    } else {
        // fill role: exactly N2/4 float4s across 44100 blocks
        int i = (bid - SCREEN_BLOCKS)*256 + tid;
        int row = i / 28;            // (t*240 + o)*112 + y
        int xq  = i % 28;
        int y = row % PH;
        int o = (row / PH) % O2;
        int rc = (y == 0) ? 0 : ((y == PH-1) ? 2 : 1);
        const float* Sp = &d_S[o*9 + rc*3];
        float v0 = Sp[0], v1 = Sp[1], v2 = Sp[2];
        float4 p;
        p.x = (xq == 0)  ? v0 : v1;
        p.y = v1; p.z = v1;
        p.w = (xq == 27) ? v2 : v1;
        float4 s;
        s.x = (p.x > 10.0f) ? 1.0f : 0.0f; if (!(p.x > 10.0f)) p.x = 0.0f;
        s.y = (p.y > 10.0f) ? 1.0f : 0.0f; if (!(p.y > 10.0f)) p.y = 0.0f;
        s.z = (p.z > 10.0f) ? 1.0f : 0.0f; if (!(p.z > 10.0f)) p.z = 0.0f;
        s.w = (p.w > 10.0f) ? 1.0f : 0.0f; if (!(p.w > 10.0f)) p.w = 0.0f;
        ((float4*)spk)[i] = s;
        ((float4*)pot)[i] = p;
    }
}

// ---------------------------------------------------------------------------
// fallback: for each candidate pooled pixel, compute the full 2x2 conv-pixel
// max exactly from gmem; if the max doesn't fire, record a true zero spike.
// ---------------------------------------------------------------------------
__global__ void fallback_kernel(const float* __restrict__ in,
                                const float* __restrict__ w1)
{
    int n = d_cand_count; if (n > CCAP) n = CCAP;
    int stride = gridDim.x * blockDim.x;
    for (int i = blockIdx.x*blockDim.x + threadIdx.x; i < n; i += stride) {
        int packed = d_cand_list[i];
        int px = packed % PH;
        int py = (packed / PH) % PH;
        int ch = (packed / (PH*PH)) % O1;
        int t  =  packed / (PH*PH*O1);
        float m = -1e30f;
        for (int yy = 0; yy < 2; ++yy) {
            for (int xx = 0; xx < 2; ++xx) {
                float pot = 0.f;
                for (int c = 0; c < C1; ++c)
                    for (int kh = 0; kh < 5; ++kh) {
                        int iy = 2*py + yy - 2 + kh;
                        if ((unsigned)iy >= HW) continue;
                        for (int kw = 0; kw < 5; ++kw) {
                            int ix = 2*px + xx - 2 + kw;
                            if ((unsigned)ix >= HW) continue;
                            pot += in[(((size_t)t*C1 + c)*HW + iy)*HW + ix]
                                 * w1[((ch*C1 + c)*5 + kh)*5 + kw];
                        }
                    }
                m = fmaxf(m, pot);
            }
        }
        if (!(m > 15.0f)) {
            int s = atomicAdd(&d_zero_count, 1);
            d_zero_list[s] = packed;
        }
    }
}

// ---------------------------------------------------------------------------
// correct: subtract each recorded zero-spike's w2 contribution from the <=3x3
// affected pot pixels across all 240 channels. Base pot is thresholded S:
//   S>10 -> exact subtraction on S, fixed up below;
//   S<=10 -> base 0, result <=0, fixup clamps to 0 (true value also 0). Exact.
// ---------------------------------------------------------------------------
__global__ void correct_kernel(const float* __restrict__ w2, float* __restrict__ pot) {
    int total  = d_zero_count * O2;
    int stride = gridDim.x * blockDim.x;
    for (int i = blockIdx.x*blockDim.x + threadIdx.x; i < total; i += stride) {
        int e = i / O2, o = i % O2;
        int packed = d_zero_list[e];
        int px = packed % PH;
        int py = (packed / PH) % PH;
        int c  = (packed / (PH*PH)) % O1;
        int t  =  packed / (PH*PH*O1);
        float* potbase = pot + ((size_t)(t*O2 + o))*PH*PH;
        const float* wb = w2 + (o*O1 + c)*9;
        #pragma unroll
        for (int kh = 0; kh < 3; ++kh) {
            int y = py + 1 - kh;
            if ((unsigned)y >= PH) continue;
            #pragma unroll
            for (int kw = 0; kw < 3; ++kw) {
                int x = px + 1 - kw;
                if ((unsigned)x >= PH) continue;
                atomicAdd(&potbase[y*PH + x], -wb[kh*3 + kw]);
            }
        }
    }
}

// ---------------------------------------------------------------------------
// fixup: only does real work if corrections happened. Re-thresholds pot and
// rewrites spk for the whole tensor (idempotent for untouched pixels).
// When d_zero_count == 0 every block exits after one cached global read.
// ---------------------------------------------------------------------------
__global__ void fixup_kernel(float* __restrict__ spk, float* __restrict__ pot) {
    if (d_zero_count == 0) return;
    const int n4 = N2/4;
    int stride = gridDim.x * blockDim.x;
    for (int i = blockIdx.x*blockDim.x + threadIdx.x; i < n4; i += stride) {
        float4 p = ((const float4*)pot)[i];
        float4 s;
        s.x = (p.x > 10.0f) ? 1.0f : 0.0f; if (!(p.x > 10.0f)) p.x = 0.0f;
        s.y = (p.y > 10.0f) ? 1.0f : 0.0f; if (!(p.y > 10.0f)) p.y = 0.0f;
        s.z = (p.z > 10.0f) ? 1.0f : 0.0f; if (!(p.z > 10.0f)) p.z = 0.0f;
        s.w = (p.w > 10.0f) ? 1.0f : 0.0f; if (!(p.w > 10.0f)) p.w = 0.0f;
        ((float4*)spk)[i] = s;
        ((float4*)pot)[i] = p;
    }
}

// ---------------------------------------------------------------------------
extern "C" void kernel_launch(void* const* d_in, const int* in_sizes, int n_in,
                              void* d_out, int out_size) {
    const float* input = (const float*)d_in[0];
    const float* w1    = (const float*)d_in[1];
    const float* w2    = (const float*)d_in[2];
    float* spk = (float*)d_out;
    float* pot = spk + (size_t)(out_size / 2);

    prep_kernel<<<O2 + 1, 32>>>(w1, w2);
    fused_kernel<<<SCREEN_BLOCKS + N2/4/256, 256>>>(input, spk, pot);
    fallback_kernel<<<512, 128>>>(input, w1);
    correct_kernel<<<960, 256>>>(w2, pot);
    fixup_kernel<<<2048, 256>>>(spk, pot);
    (void)in_sizes; (void)n_in;
}

// round 10
// speedup vs baseline: 3.7409x; 1.0345x over previous
#include <cuda_runtime.h>
#include <cstdint>

// Problem constants (fixed shapes from reference)
#define T_IMG 15
#define C1    6
#define HW    224
#define O1    30
#define O2    240
#define PH    112                      // pooled / layer-2 spatial size
#define N2    (T_IMG*O2*PH*PH)         // 45,158,400 elements per output tensor
#define ZCAP  (T_IMG*O1*PH*PH)
#define NSCR  (T_IMG*PH)               // 1680 screen blocks
#define NFILL (N2/4/256)               // 44100 fill blocks
#define GRID_FUSED (NSCR*27 + (NFILL - NSCR*26))   // 45780

// Scratch (device globals — no allocation allowed)
__device__ float d_S[O2*9];            // per-o border-class full sums of w2
__device__ int   d_zero_count;
__device__ int   d_zero_list[ZCAP];

// ---------------------------------------------------------------------------
// prep: reset counter; build S[o][rc][cc] = sum over border-allowed (kh,kw)
// and all c of w2 (zero padding kills kernel rows/cols at edges).
// rc/cc: 0 -> coord==0 (k in {1,2}); 1 -> interior; 2 -> coord==PH-1 (k in {0,1})
// ---------------------------------------------------------------------------
__global__ void prep_kernel(const float* __restrict__ w2) {
    int o = blockIdx.x;
    int j = threadIdx.x;
    if (o == 0 && j == 9) d_zero_count = 0;
    if (j < 9) {
        int rc = j / 3, cc = j % 3;
        int kh_lo = (rc == 0) ? 1 : 0;
        int kh_hi = (rc == 2) ? 1 : 2;
        int kw_lo = (cc == 0) ? 1 : 0;
        int kw_hi = (cc == 2) ? 1 : 2;
        float s = 0.f;
        for (int kh = kh_lo; kh <= kh_hi; ++kh)
            for (int kw = kw_lo; kw <= kw_hi; ++kw)
                for (int c = 0; c < O1; ++c)
                    s += w2[((o*O1 + c)*3 + kh)*3 + kw];
        d_S[o*9 + j] = s;
    }
}

// ---------------------------------------------------------------------------
// fused kernel, interleaved block roles (1 screen block per 27-block group so
// the latency-bound screening hides under the DRAM-bound fill stream):
//
// SCREEN role (one (t, pooled row py) each): compute B = zero-padded 5x5x6
//   box-sum of the input at the representative conv pixel (2py,2px). Since
//   input >= 0, pot_o(rep) >= wmin_o * B; if that exceeds 15 the pooled pixel
//   provably fires (pool-max >= rep). Otherwise resolve EXACTLY inline: full
//   2x2 conv-pixel max from gmem; true zero spikes -> d_zero_list. Negative
//   wmin_o => product <= 0 => always resolved exactly => sound for any weights.
//
// FILL role: pot2 assuming all pooled spikes fire = S[o][rc(y)][cc(x)],
//   thresholded at 10; writes BOTH pot and spk final in one coalesced
//   float4 pass with evict-first stores.
// ---------------------------------------------------------------------------
__global__ void __launch_bounds__(256) fused_kernel(
    const float* __restrict__ in, const float* __restrict__ w1,
    float* __restrict__ spk, float* __restrict__ pot)
{
    const int bid = blockIdx.x;
    const int tid = threadIdx.x;
    const int g = bid / 27, l = bid - g * 27;

    if (l == 26 && g < NSCR) {
        // ------------------------- SCREEN role -------------------------
        __shared__ float sV[228];
        __shared__ float swmin[O1];
        __shared__ float swminmin;

        const int t  = g / PH;
        const int py = g % PH;

        // per-filter min of w1 (30 filters x 150 weights), L1-hot
        if (tid < O1) {
            const float* w = w1 + tid * (C1*25);
            float m = w[0];
            for (int k = 1; k < C1*25; ++k) m = fminf(m, w[k]);
            swmin[tid] = m;
        }
        __syncthreads();
        if (tid == 0) {
            float m = swmin[0];
            #pragma unroll
            for (int o = 1; o < O1; ++o) m = fminf(m, swmin[o]);
            swminmin = m;
        }

        // column sums over the 5 conv rows x 6 channels (zero padding)
        const float* base = in + (size_t)t * C1*HW*HW;
        if (tid < 228) {
            int x = tid - 2;
            float s = 0.f;
            if ((unsigned)x < HW) {
                int y0 = 2*py - 2;
                #pragma unroll
                for (int r = 0; r < 5; ++r) {
                    int y = y0 + r;
                    if ((unsigned)y < HW) {
                        #pragma unroll
                        for (int c = 0; c < C1; ++c)
                            s += base[(c*HW + y)*HW + x];
                    }
                }
            }
            sV[tid] = s;
        }
        __syncthreads();

        if (tid >= PH) return;
        const int px = tid;
        float B = sV[2*px] + sV[2*px+1] + sV[2*px+2] + sV[2*px+3] + sV[2*px+4];
        if (swminmin * B > 15.0f) return;     // every filter provably fires

        for (int o = 0; o < O1; ++o) {
            if (swmin[o] * B > 15.0f) continue;
            // exact inline resolution: full 2x2 conv-pixel max
            float m = -1e30f;
            for (int yy = 0; yy < 2; ++yy) {
                for (int xx = 0; xx < 2; ++xx) {
                    float p = 0.f;
                    for (int c = 0; c < C1; ++c)
                        for (int kh = 0; kh < 5; ++kh) {
                            int iy = 2*py + yy - 2 + kh;
                            if ((unsigned)iy >= HW) continue;
                            for (int kw = 0; kw < 5; ++kw) {
                                int ix = 2*px + xx - 2 + kw;
                                if ((unsigned)ix >= HW) continue;
                                p += base[((size_t)c*HW + iy)*HW + ix]
                                   * w1[((o*C1 + c)*5 + kh)*5 + kw];
                            }
                        }
                    m = fmaxf(m, p);
                }
            }
            if (!(m > 15.0f)) {
                int s = atomicAdd(&d_zero_count, 1);
                d_zero_list[s] = ((t*O1 + o)*PH + py)*PH + px;
            }
        }
    } else {
        // -------------------------- FILL role --------------------------
        int fidx = (g < NSCR) ? (g*26 + l) : (NSCR*26 + bid - NSCR*27);
        int i = fidx * 256 + tid;
        int row = i / 28;            // (t*240 + o)*112 + y
        int xq  = i % 28;
        int y = row % PH;
        int o = (row / PH) % O2;
        int rc = (y == 0) ? 0 : ((y == PH-1) ? 2 : 1);
        const float* Sp = &d_S[o*9 + rc*3];
        float v0 = Sp[0], v1 = Sp[1], v2 = Sp[2];
        float4 p;
        p.x = (xq == 0)  ? v0 : v1;
        p.y = v1; p.z = v1;
        p.w = (xq == 27) ? v2 : v1;
        float4 s;
        s.x = (p.x > 10.0f) ? 1.0f : 0.0f; if (!(p.x > 10.0f)) p.x = 0.0f;
        s.y = (p.y > 10.0f) ? 1.0f : 0.0f; if (!(p.y > 10.0f)) p.y = 0.0f;
        s.z = (p.z > 10.0f) ? 1.0f : 0.0f; if (!(p.z > 10.0f)) p.z = 0.0f;
        s.w = (p.w > 10.0f) ? 1.0f : 0.0f; if (!(p.w > 10.0f)) p.w = 0.0f;
        __stcs(((float4*)spk) + i, s);
        __stcs(((float4*)pot) + i, p);
    }
}

// ---------------------------------------------------------------------------
// correct: subtract each recorded zero-spike's w2 contribution from the <=3x3
// affected pot pixels across all 240 channels. Base pot is thresholded S:
//   S>10 -> exact subtraction on S, fixed up below;
//   S<=10 -> base 0, result <=0, fixup clamps to 0 (true value also 0). Exact.
// ---------------------------------------------------------------------------
__global__ void correct_kernel(const float* __restrict__ w2, float* __restrict__ pot) {
    int total  = d_zero_count * O2;
    int stride = gridDim.x * blockDim.x;
    for (int i = blockIdx.x*blockDim.x + threadIdx.x; i < total; i += stride) {
        int e = i / O2, o = i % O2;
        int packed = d_zero_list[e];
        int px = packed % PH;
        int py = (packed / PH) % PH;
        int c  = (packed / (PH*PH)) % O1;
        int t  =  packed / (PH*PH*O1);
        float* potbase = pot + ((size_t)(t*O2 + o))*PH*PH;
        const float* wb = w2 + (o*O1 + c)*9;
        #pragma unroll
        for (int kh = 0; kh < 3; ++kh) {
            int y = py + 1 - kh;
            if ((unsigned)y >= PH) continue;
            #pragma unroll
            for (int kw = 0; kw < 3; ++kw) {
                int x = px + 1 - kw;
                if ((unsigned)x >= PH) continue;
                atomicAdd(&potbase[y*PH + x], -wb[kh*3 + kw]);
            }
        }
    }
}

// ---------------------------------------------------------------------------
// fixup: only does real work if corrections happened. Re-thresholds pot and
// rewrites spk for the whole tensor (idempotent for untouched pixels).
// When d_zero_count == 0 every block exits after one cached global read.
// ---------------------------------------------------------------------------
__global__ void fixup_kernel(float* __restrict__ spk, float* __restrict__ pot) {
    if (d_zero_count == 0) return;
    const int n4 = N2/4;
    int stride = gridDim.x * blockDim.x;
    for (int i = blockIdx.x*blockDim.x + threadIdx.x; i < n4; i += stride) {
        float4 p = ((const float4*)pot)[i];
        float4 s;
        s.x = (p.x > 10.0f) ? 1.0f : 0.0f; if (!(p.x > 10.0f)) p.x = 0.0f;
        s.y = (p.y > 10.0f) ? 1.0f : 0.0f; if (!(p.y > 10.0f)) p.y = 0.0f;
        s.z = (p.z > 10.0f) ? 1.0f : 0.0f; if (!(p.z > 10.0f)) p.z = 0.0f;
        s.w = (p.w > 10.0f) ? 1.0f : 0.0f; if (!(p.w > 10.0f)) p.w = 0.0f;
        ((float4*)spk)[i] = s;
        ((float4*)pot)[i] = p;
    }
}

// ---------------------------------------------------------------------------
extern "C" void kernel_launch(void* const* d_in, const int* in_sizes, int n_in,
                              void* d_out, int out_size) {
    const float* input = (const float*)d_in[0];
    const float* w1    = (const float*)d_in[1];
    const float* w2    = (const float*)d_in[2];
    float* spk = (float*)d_out;
    float* pot = spk + (size_t)(out_size / 2);

    prep_kernel<<<O2, 32>>>(w2);
    fused_kernel<<<GRID_FUSED, 256>>>(input, w1, spk, pot);
    correct_kernel<<<480, 256>>>(w2, pot);
    fixup_kernel<<<512, 256>>>(spk, pot);
    (void)in_sizes; (void)n_in;
}